// round 17
// baseline (speedup 1.0000x reference)
#include <cuda_runtime.h>
#include <cuda_bf16.h>
#include <math.h>
#include <cstdint>

#define BB 32
#define CC 512
#define NN 1024
#define RR 64
#define EPS 1e-5f
#define SCALE 0.04419417382415922f
typedef uint32_t u32;

__device__ __forceinline__ u32 pbf2(float lo, float hi) {   // word = {lo16, hi16}
    u32 r; asm("cvt.rn.bf16x2.f32 %0,%1,%2;" : "=r"(r) : "f"(hi), "f"(lo));
    return r;
}
__device__ __forceinline__ u32 smem_u32p(const void* p) {
    u32 a;
    asm("{ .reg .u64 t; cvta.to.shared.u64 t,%1; cvt.u32.u64 %0,t; }" : "=r"(a) : "l"(p));
    return a;
}
#define MMAB(d,a0,a1,a2,a3,b0,b1) \
    asm volatile("mma.sync.aligned.m16n8k16.row.col.f32.bf16.bf16.f32 " \
        "{%0,%1,%2,%3},{%4,%5,%6,%7},{%8,%9},{%0,%1,%2,%3};" \
        : "+f"((d)[0]),"+f"((d)[1]),"+f"((d)[2]),"+f"((d)[3]) \
        : "r"(a0),"r"(a1),"r"(a2),"r"(a3),"r"(b0),"r"(b1))
#define CP16(dst,src) asm volatile("cp.async.ca.shared.global [%0],[%1],16;" :: "r"(dst), "l"(src))
#define CPCOMMIT()    asm volatile("cp.async.commit_group;")
#define CPWAIT1()     asm volatile("cp.async.wait_group 1;")
#define CPWAIT0()     asm volatile("cp.async.wait_group 0;")

// bf16 pair-packed tensors:
// d_tb/d_pb: [b][n][32] r-pair words (t pre-scaled by SCALE)
// d_gb:      [b][r][512] n-pair words
// d_yh/d_yl: [b][n][32] r-pair words, hi/lo split of y
__device__ __align__(16) u32 d_tb[BB * NN * 32];
__device__ __align__(16) u32 d_pb[BB * NN * 32];
__device__ __align__(16) u32 d_gb[BB * RR * 512];
__device__ __align__(16) u32 d_yh[BB * NN * 32];
__device__ __align__(16) u32 d_yl[BB * NN * 32];
// packed bf16 weights: stacked [Wt*SCALE; Wp; Wg] pair-words [192][256], Wz [512][32]
__device__ __align__(16) u32 wsp_h[192 * 256];
__device__ __align__(16) u32 wz_h[512 * 32];

// ---------------------------------------------------------------------------
// K0: pack all weights to bf16 pair-words. 64 x 256 threads.
// ---------------------------------------------------------------------------
__global__ void split_kernel(const float* __restrict__ Wt,
                             const float* __restrict__ Wp,
                             const float* __restrict__ Wg,
                             const float* __restrict__ Wz)
{
    int slot = blockIdx.x * 256 + threadIdx.x;
    if (slot < 12288) {
        int row = slot >> 6;
        int c8  = (slot & 63) * 8;
        const float* src = (row < 64) ? (Wt + (size_t)row * CC)
                         : (row < 128) ? (Wp + (size_t)(row - 64) * CC)
                                       : (Wg + (size_t)(row - 128) * CC);
        float sc = (row < 64) ? SCALE : 1.0f;
        float4 v0 = *reinterpret_cast<const float4*>(src + c8);
        float4 v1 = *reinterpret_cast<const float4*>(src + c8 + 4);
        uint4 wh = {pbf2(v0.x * sc, v0.y * sc), pbf2(v0.z * sc, v0.w * sc),
                    pbf2(v1.x * sc, v1.y * sc), pbf2(v1.z * sc, v1.w * sc)};
        *reinterpret_cast<uint4*>(wsp_h + row * 256 + c8 / 2) = wh;
    } else {
        int s = slot - 12288;
        int row = s >> 3;
        int r8  = (s & 7) * 8;
        const float* src = Wz + (size_t)row * RR + r8;
        float4 v0 = *reinterpret_cast<const float4*>(src);
        float4 v1 = *reinterpret_cast<const float4*>(src + 4);
        uint4 wh = {pbf2(v0.x, v0.y), pbf2(v0.z, v0.w),
                    pbf2(v1.x, v1.y), pbf2(v1.z, v1.w)};
        *reinterpret_cast<uint4*>(wz_h + row * 32 + r8 / 2) = wh;
    }
}

// ---------------------------------------------------------------------------
// K1: projections via mma.sync bf16, single term. (unchanged)
// ---------------------------------------------------------------------------
__global__ __launch_bounds__(256) void proj_kernel(
    const float* __restrict__ x,
    const float* __restrict__ bt, const float* __restrict__ bp,
    const float* __restrict__ bg)
{
    __shared__ u32 whS[192][20];
    __shared__ u32 xhS[16][132];

    const int b  = blockIdx.x >> 3;
    const int n0 = (blockIdx.x & 7) << 7;
    const int tid = threadIdx.x, wid = tid >> 5, lane = tid & 31;
    const int wm = wid & 3, wn = wid >> 2;
    const int gq = lane >> 2, tg = lane & 3;

    float acc[3][8][4];
#pragma unroll
    for (int m = 0; m < 3; m++)
#pragma unroll
        for (int n = 0; n < 8; n++)
#pragma unroll
            for (int j = 0; j < 4; j++) acc[m][n][j] = 0.f;

    const float* xb = x + (size_t)b * CC * NN + n0;

    for (int kc = 0; kc < 16; kc++) {
        const int k0 = kc * 32;
#pragma unroll
        for (int it = 0; it < 3; it++) {
            int slot = it * 256 + tid;
            int r = slot >> 2, seg = slot & 3;
            *reinterpret_cast<uint4*>(&whS[r][seg * 4]) =
                *reinterpret_cast<const uint4*>(wsp_h + r * 256 + kc * 16 + seg * 4);
        }
#pragma unroll
        for (int it = 0; it < 2; it++) {
            int slot = it * 256 + tid;
            int cp = slot >> 5, n4 = (slot & 31) * 4;
            float4 e = *reinterpret_cast<const float4*>(xb + (size_t)(k0 + 2 * cp) * NN + n4);
            float4 o = *reinterpret_cast<const float4*>(xb + (size_t)(k0 + 2 * cp + 1) * NN + n4);
            uint4 hw = {pbf2(e.x, o.x), pbf2(e.y, o.y), pbf2(e.z, o.z), pbf2(e.w, o.w)};
            *reinterpret_cast<uint4*>(&xhS[cp][n4]) = hw;
        }
        __syncthreads();

#pragma unroll
        for (int ks = 0; ks < 2; ks++) {
            u32 ah[3][4];
#pragma unroll
            for (int m = 0; m < 3; m++) {
                int rb = (wm + m * 4) * 16;
                ah[m][0] = whS[rb + gq][ks * 8 + tg];
                ah[m][1] = whS[rb + gq + 8][ks * 8 + tg];
                ah[m][2] = whS[rb + gq][ks * 8 + tg + 4];
                ah[m][3] = whS[rb + gq + 8][ks * 8 + tg + 4];
            }
#pragma unroll
            for (int nt = 0; nt < 8; nt++) {
                int col = wn * 64 + nt * 8 + gq;
                u32 b0h = xhS[ks * 8 + tg][col];
                u32 b1h = xhS[ks * 8 + tg + 4][col];
#pragma unroll
                for (int m = 0; m < 3; m++)
                    MMAB(acc[m][nt], ah[m][0], ah[m][1], ah[m][2], ah[m][3], b0h, b1h);
            }
        }
        __syncthreads();
    }

    const int r0 = wm * 16 + gq, r1 = r0 + 8;
    const bool evn = !(gq & 1);
    float bb0[3] = {bt[r0] * SCALE, bp[r0], bg[r0]};
    float bb1[3] = {bt[r1] * SCALE, bp[r1], bg[r1]};

#pragma unroll
    for (int nt = 0; nt < 8; nt++) {
        int n = n0 + wn * 64 + nt * 8 + 2 * tg;
#pragma unroll
        for (int m = 0; m < 2; m++) {
            float c0 = acc[m][nt][0] + bb0[m], c1 = acc[m][nt][1] + bb0[m];
            float c2 = acc[m][nt][2] + bb1[m], c3 = acc[m][nt][3] + bb1[m];
            float o0 = __shfl_xor_sync(0xffffffffu, c0, 4);
            float o1 = __shfl_xor_sync(0xffffffffu, c1, 4);
            float o2 = __shfl_xor_sync(0xffffffffu, c2, 4);
            float o3 = __shfl_xor_sync(0xffffffffu, c3, 4);
            u32* db = (m == 0) ? d_tb : d_pb;
            if (evn) {
                int wi = r0 >> 1;
                db[((size_t)b * NN + n) * 32 + wi]     = pbf2(c0, o0);
                db[((size_t)b * NN + n + 1) * 32 + wi] = pbf2(c1, o1);
            } else {
                int wi = r1 >> 1;
                db[((size_t)b * NN + n) * 32 + wi]     = pbf2(o2, c2);
                db[((size_t)b * NN + n + 1) * 32 + wi] = pbf2(o3, c3);
            }
        }
        {
            float c0 = acc[2][nt][0] + bb0[2], c1 = acc[2][nt][1] + bb0[2];
            float c2 = acc[2][nt][2] + bb1[2], c3 = acc[2][nt][3] + bb1[2];
            int wi = ((n0 + wn * 64) >> 1) + nt * 4 + tg;
            d_gb[((size_t)b * RR + r0) * 512 + wi] = pbf2(c0, c1);
            d_gb[((size_t)b * RR + r1) * 512 + wi] = pbf2(c2, c3);
        }
    }
}

// ---------------------------------------------------------------------------
// K2: attention, bf16 m16n8k16, cp.async double-buffered. (unchanged)
// ---------------------------------------------------------------------------
__global__ __launch_bounds__(256, 2) void attn_kernel()
{
    extern __shared__ u32 smu[];
    u32 (*tS)[36] = (u32(*)[36])smu;
    u32 (*pS)[36] = (u32(*)[36])(smu + 128 * 36);
    u32 (*gS)[36] = (u32(*)[36])(smu + 256 * 36);

    const int b = blockIdx.y, n0 = blockIdx.x * 128;
    const int tid = threadIdx.x, wid = tid >> 5, lane = tid & 31;
    const int gq = lane >> 2, tg = lane & 3;
    const int wn0 = wid * 16;

    const u32* tb = d_tb + ((size_t)b * NN + n0) * 32;
#pragma unroll
    for (int it = 0; it < 4; it++) {
        int i = it * 256 + tid;
        int n = i >> 3, q = (i & 7) * 4;
        CP16(smem_u32p(&tS[n][q]), tb + (size_t)n * 32 + q);
    }
    CPCOMMIT();

    const u32* pb = d_pb + (size_t)b * NN * 32;
    const u32* gb = d_gb + (size_t)b * RR * 512;

    auto stage = [&](int buf, int m0) {
#pragma unroll
        for (int it = 0; it < 2; it++) {
            int i = it * 256 + tid;
            int m = i >> 3, q = (i & 7) * 4;
            CP16(smem_u32p(&pS[buf * 64 + m][q]), pb + (size_t)(m0 + m) * 32 + q);
        }
#pragma unroll
        for (int it = 0; it < 2; it++) {
            int i = it * 256 + tid;
            int r = i >> 3, q = (i & 7) * 4;
            CP16(smem_u32p(&gS[buf * 64 + r][q]), gb + (size_t)r * 512 + (m0 >> 1) + q);
        }
    };

    float yacc[8][4];
#pragma unroll
    for (int i = 0; i < 8; i++)
#pragma unroll
        for (int j = 0; j < 4; j++) yacc[i][j] = 0.f;
    float rsum_lo = 0.f, rsum_hi = 0.f;

    stage(0, 0);
    CPCOMMIT();

    for (int mc = 0; mc < 16; mc++) {
        const int cb = mc & 1;
        if (mc < 15) { stage(cb ^ 1, (mc + 1) * 64); CPCOMMIT(); CPWAIT1(); }
        else CPWAIT0();
        __syncthreads();

        float s[8][4];
#pragma unroll
        for (int i = 0; i < 8; i++)
#pragma unroll
            for (int j = 0; j < 4; j++) s[i][j] = 0.f;
#pragma unroll
        for (int ks = 0; ks < 4; ks++) {
            u32 a0 = tS[wn0 + gq][ks * 8 + tg];
            u32 a1 = tS[wn0 + gq + 8][ks * 8 + tg];
            u32 a2 = tS[wn0 + gq][ks * 8 + tg + 4];
            u32 a3 = tS[wn0 + gq + 8][ks * 8 + tg + 4];
#pragma unroll
            for (int mb = 0; mb < 8; mb++) {
                u32 b0 = pS[cb * 64 + mb * 8 + gq][ks * 8 + tg];
                u32 b1 = pS[cb * 64 + mb * 8 + gq][ks * 8 + tg + 4];
                MMAB(s[mb], a0, a1, a2, a3, b0, b1);
            }
        }

        float lsum_lo = 0.f, lsum_hi = 0.f;
#pragma unroll
        for (int mb = 0; mb < 8; mb++) {
            float e0 = __expf(s[mb][0]), e1 = __expf(s[mb][1]);
            float e2 = __expf(s[mb][2]), e3 = __expf(s[mb][3]);
            lsum_lo += e0 + e1; lsum_hi += e2 + e3;
            s[mb][0] = e0; s[mb][1] = e1; s[mb][2] = e2; s[mb][3] = e3;
        }
        lsum_lo += __shfl_xor_sync(0xffffffffu, lsum_lo, 1);
        lsum_lo += __shfl_xor_sync(0xffffffffu, lsum_lo, 2);
        lsum_hi += __shfl_xor_sync(0xffffffffu, lsum_hi, 1);
        lsum_hi += __shfl_xor_sync(0xffffffffu, lsum_hi, 2);
        rsum_lo += lsum_lo; rsum_hi += lsum_hi;

#pragma unroll
        for (int ks = 0; ks < 4; ks++) {
            u32 a0 = pbf2(s[2 * ks][0],     s[2 * ks][1]);
            u32 a1 = pbf2(s[2 * ks][2],     s[2 * ks][3]);
            u32 a2 = pbf2(s[2 * ks + 1][0], s[2 * ks + 1][1]);
            u32 a3 = pbf2(s[2 * ks + 1][2], s[2 * ks + 1][3]);
#pragma unroll
            for (int rb = 0; rb < 8; rb++) {
                u32 b0 = gS[cb * 64 + rb * 8 + gq][ks * 8 + tg];
                u32 b1 = gS[cb * 64 + rb * 8 + gq][ks * 8 + tg + 4];
                MMAB(yacc[rb], a0, a1, a2, a3, b0, b1);
            }
        }
        __syncthreads();
    }

    float inv_lo = 1.f / rsum_lo, inv_hi = 1.f / rsum_hi;
    u32* yhb = d_yh + ((size_t)b * NN + n0) * 32;
    u32* ylb = d_yl + ((size_t)b * NN + n0) * 32;
#pragma unroll
    for (int rb = 0; rb < 8; rb++) {
        int wi = rb * 4 + tg;
        float y0 = yacc[rb][0] * inv_lo, y1 = yacc[rb][1] * inv_lo;
        float y2 = yacc[rb][2] * inv_hi, y3 = yacc[rb][3] * inv_hi;
        float f0 = __bfloat162float(__float2bfloat16(y0));
        float f1 = __bfloat162float(__float2bfloat16(y1));
        float f2 = __bfloat162float(__float2bfloat16(y2));
        float f3 = __bfloat162float(__float2bfloat16(y3));
        yhb[(size_t)(wn0 + gq) * 32 + wi]     = pbf2(f0, f1);
        ylb[(size_t)(wn0 + gq) * 32 + wi]     = pbf2(y0 - f0, y1 - f1);
        yhb[(size_t)(wn0 + gq + 8) * 32 + wi] = pbf2(f2, f3);
        ylb[(size_t)(wn0 + gq + 8) * 32 + wi] = pbf2(y2 - f2, y3 - f3);
    }
}

// ---------------------------------------------------------------------------
// K3: z = Wz @ y^T, bf16 2-term, + bias/BN/residual.
// Block = (b, 128c, 64n). z bounced through smem so the x-read and out-write
// are row-major float4 COALESCED. One 36864-B buffer holds BOTH layouts:
//   phase A (staging): Wz[0,18432) | yh[18432,27648) | yl[27648,36864)
//   phase B (epilogue): zS 128x66 f32 = 33792 B, overlaid at base after sync.
// ---------------------------------------------------------------------------
__global__ __launch_bounds__(256) void out_kernel(
    const float* __restrict__ x, const float* __restrict__ bz,
    const float* __restrict__ gamma, const float* __restrict__ beta,
    const float* __restrict__ bn_mean, const float* __restrict__ bn_var,
    float* __restrict__ out)
{
    __shared__ __align__(16) char smraw[36864];
    u32 (*wzhS)[36] = (u32(*)[36])smraw;
    u32 (*yhS)[36]  = (u32(*)[36])(smraw + 18432);
    u32 (*ylS)[36]  = (u32(*)[36])(smraw + 27648);
    float (*zS)[66] = (float(*)[66])smraw;

    const int b = blockIdx.z, c0 = blockIdx.y * 128, n0 = blockIdx.x * 64;
    const int tid = threadIdx.x, w = tid >> 5, lane = tid & 31;
    const int gq = lane >> 2, tg = lane & 3;

    // ---- phase A: stage Wz + y
#pragma unroll
    for (int it = 0; it < 4; it++) {
        int slot = it * 256 + tid;
        int r = slot >> 3, q4 = (slot & 7) * 4;
        *reinterpret_cast<uint4*>(&wzhS[r][q4]) =
            *reinterpret_cast<const uint4*>(wz_h + (size_t)(c0 + r) * 32 + q4);
    }
    const u32* yhb = d_yh + ((size_t)b * NN + n0) * 32;
    const u32* ylb = d_yl + ((size_t)b * NN + n0) * 32;
#pragma unroll
    for (int it = 0; it < 2; it++) {
        int slot = it * 256 + tid;
        int n = slot >> 3, q4 = (slot & 7) * 4;
        *reinterpret_cast<uint4*>(&yhS[n][q4]) =
            *reinterpret_cast<const uint4*>(yhb + (size_t)n * 32 + q4);
        *reinterpret_cast<uint4*>(&ylS[n][q4]) =
            *reinterpret_cast<const uint4*>(ylb + (size_t)n * 32 + q4);
    }
    __syncthreads();

    float acc[8][4];
#pragma unroll
    for (int i = 0; i < 8; i++)
#pragma unroll
        for (int j = 0; j < 4; j++) acc[i][j] = 0.f;

    const int cr = w * 16;
#pragma unroll
    for (int kw = 0; kw < 4; kw++) {
        u32 ah0 = wzhS[cr + gq][kw * 8 + tg],     ah1 = wzhS[cr + gq + 8][kw * 8 + tg];
        u32 ah2 = wzhS[cr + gq][kw * 8 + tg + 4], ah3 = wzhS[cr + gq + 8][kw * 8 + tg + 4];
#pragma unroll
        for (int nt = 0; nt < 8; nt++) {
            u32 b0h = yhS[nt * 8 + gq][kw * 8 + tg];
            u32 b1h = yhS[nt * 8 + gq][kw * 8 + tg + 4];
            u32 b0l = ylS[nt * 8 + gq][kw * 8 + tg];
            u32 b1l = ylS[nt * 8 + gq][kw * 8 + tg + 4];
            MMAB(acc[nt], ah0, ah1, ah2, ah3, b0h, b1h);
            MMAB(acc[nt], ah0, ah1, ah2, ah3, b0l, b1l);
        }
    }
    __syncthreads();   // all fragment reads of staging done before overlay

    // ---- phase B: z fragments -> smem tile
#pragma unroll
    for (int nt = 0; nt < 8; nt++) {
        int nl = nt * 8 + 2 * tg;
        *reinterpret_cast<float2*>(&zS[cr + gq][nl])     = make_float2(acc[nt][0], acc[nt][1]);
        *reinterpret_cast<float2*>(&zS[cr + gq + 8][nl]) = make_float2(acc[nt][2], acc[nt][3]);
    }
    __syncthreads();

    // coalesced epilogue: 128 rows x 16 float4 = 2048 slots / 256 thr = 8 its
    const size_t xbase = (size_t)b * CC * NN + n0;
#pragma unroll
    for (int it = 0; it < 8; it++) {
        int slot = it * 256 + tid;
        int row = slot >> 4, q = (slot & 15) * 4;
        int c = c0 + row;
        float a   = rsqrtf(bn_var[c] + EPS) * gamma[c];
        float off = (bz[c] - bn_mean[c]) * a + beta[c];
        const float4 xv = __ldcs(reinterpret_cast<const float4*>(x + xbase + (size_t)c * NN + q));
        float4 o;
        o.x = zS[row][q + 0] * a + off + xv.x;
        o.y = zS[row][q + 1] * a + off + xv.y;
        o.z = zS[row][q + 2] * a + off + xv.z;
        o.w = zS[row][q + 3] * a + off + xv.w;
        __stcs(reinterpret_cast<float4*>(out + xbase + (size_t)c * NN + q), o);
    }
}

#define ATTN_SMEM (384 * 36 * 4)

extern "C" void kernel_launch(void* const* d_in, const int* in_sizes, int n_in,
                              void* d_out, int out_size)
{
    (void)in_sizes; (void)n_in; (void)out_size;
    const float* x = (const float*)d_in[0];
    const float* Wt = (const float*)d_in[1];  const float* bt = (const float*)d_in[2];
    const float* Wp = (const float*)d_in[3];  const float* bp = (const float*)d_in[4];
    const float* Wg = (const float*)d_in[5];  const float* bg = (const float*)d_in[6];
    const float* Wz = (const float*)d_in[7];  const float* bz = (const float*)d_in[8];
    const float* gamma = (const float*)d_in[9];  const float* beta = (const float*)d_in[10];
    const float* bn_mean = (const float*)d_in[11]; const float* bn_var = (const float*)d_in[12];
    float* out = (float*)d_out;

    cudaFuncSetAttribute(attn_kernel, cudaFuncAttributeMaxDynamicSharedMemorySize, ATTN_SMEM);

    split_kernel<<<64, 256>>>(Wt, Wp, Wg, Wz);
    proj_kernel<<<256, 256>>>(x, bt, bp, bg);
    attn_kernel<<<dim3(8, 32), 256, ATTN_SMEM>>>();
    out_kernel<<<dim3(16, 4, 32), 256>>>(x, bz, gamma, beta, bn_mean, bn_var, out);
}